// round 1
// baseline (speedup 1.0000x reference)
#include <cuda_runtime.h>
#include <math.h>

#define Bn    8
#define Hdim  512
#define Wdim  512
#define NPIX  (Hdim*Wdim)
#define NBINS 256

// Per-image-stream pyramid arena (elements):
// L0: 8*262144 @0, L1: 8*65536 @2097152, L2: 8*16384 @2621440,
// L3: 8*4096 @2752512, L4: 8*1024 @2785280, total 2793472
__device__ float d_Lp[2793472];
__device__ float d_Lt[2793472];
__device__ int   d_histp[Bn*3*NBINS];
__device__ int   d_histt[Bn*3*NBINS];
__device__ float d_l1sum;
__device__ float d_ssim_sum[Bn*5];
__device__ float d_cs_sum[Bn*5];
__device__ float d_win[25];

// ---------------- init: zero accumulators + build Gaussian window ----------
__global__ void k_init()
{
    int t = blockIdx.x*blockDim.x + threadIdx.x;
    int n = gridDim.x*blockDim.x;
    for (int i = t; i < Bn*3*NBINS; i += n) { d_histp[i] = 0; d_histt[i] = 0; }
    if (t < Bn*5) { d_ssim_sum[t] = 0.f; d_cs_sum[t] = 0.f; }
    if (t == 0) {
        d_l1sum = 0.f;
        double g[5], s = 0.0;
        for (int i = 0; i < 5; i++) { double x = (double)(i - 2); g[i] = exp(-(x*x)/4.5); s += g[i]; }
        for (int i = 0; i < 5; i++) g[i] /= s;
        for (int i = 0; i < 5; i++)
            for (int j = 0; j < 5; j++)
                d_win[i*5 + j] = (float)(g[i]*g[j]);
    }
}

// ---------------- RGB -> normalized LAB helpers ----------------------------
__device__ __forceinline__ float srgb_lin(float x)
{
    if (x <= 0.04045f) return x * (1.f/12.92f);
    float y = (fmaxf(x, 1e-4f) + 0.055f) * (1.f/1.055f);
    return __powf(y, 2.4f);
}

__device__ __forceinline__ float f_lab(float t)
{
    const float e3 = 0.008856451679035631f;   // (6/29)^3
    if (t <= e3) return t * (841.f/108.f) + (4.f/29.f);
    return __powf(fmaxf(t, 1e-4f), 1.f/3.f);
}

__device__ __forceinline__ void rgb2lab_norm(float r, float g, float b,
                                             float& L, float& A, float& Bc)
{
    float lr = srgb_lin(r), lg = srgb_lin(g), lb = srgb_lin(b);
    float X = lr*0.412453f + lg*0.357580f + lb*0.180423f;
    float Y = lr*0.212671f + lg*0.715160f + lb*0.072169f;
    float Z = lr*0.019334f + lg*0.119193f + lb*0.950227f;
    X *= (1.f/0.950456f);
    Z *= (1.f/1.088754f);
    float fx = f_lab(X), fy = f_lab(Y), fz = f_lab(Z);
    float Ll = 116.f*fy - 16.f;
    float Aa = 500.f*(fx - fy);
    float Bb = 200.f*(fy - fz);
    L  = fminf(fmaxf(Ll * 0.01f,                 0.f), 1.f);
    A  = fminf(fmaxf((Aa*(1.f/110.f)+1.f)*0.5f,  0.f), 1.f);
    Bc = fminf(fmaxf((Bb*(1.f/110.f)+1.f)*0.5f,  0.f), 1.f);
}

__device__ __forceinline__ int bin_of(float v)
{
    int b = (int)(v * 256.f);
    return b > 255 ? 255 : b;
}

// ---------------- fused LAB + histogram + L1 + L-channel store -------------
__global__ void k_lab(const float* __restrict__ pred, const float* __restrict__ tgt)
{
    __shared__ int   sh[6*NBINS];
    __shared__ float red[8];
    int b   = blockIdx.y;
    int tid = threadIdx.x;
    int p   = blockIdx.x*256 + tid;

    for (int i = tid; i < 6*NBINS; i += 256) sh[i] = 0;
    __syncthreads();

    const float* ip = pred + (size_t)b*3*NPIX + p;
    const float* it = tgt  + (size_t)b*3*NPIX + p;

    float pl, pa, pb, tl, ta, tb;
    rgb2lab_norm(ip[0], ip[NPIX], ip[2*NPIX], pl, pa, pb);
    rgb2lab_norm(it[0], it[NPIX], it[2*NPIX], tl, ta, tb);

    d_Lp[(size_t)b*NPIX + p] = pl;
    d_Lt[(size_t)b*NPIX + p] = tl;

    atomicAdd(&sh[0*NBINS + bin_of(pl)], 1);
    atomicAdd(&sh[1*NBINS + bin_of(pa)], 1);
    atomicAdd(&sh[2*NBINS + bin_of(pb)], 1);
    atomicAdd(&sh[3*NBINS + bin_of(tl)], 1);
    atomicAdd(&sh[4*NBINS + bin_of(ta)], 1);
    atomicAdd(&sh[5*NBINS + bin_of(tb)], 1);

    float l1 = fabsf(pl-tl) + fabsf(pa-ta) + fabsf(pb-tb);

    __syncthreads();   // histogram atomics complete

    // flush per-block histograms
    for (int i = tid; i < 3*NBINS; i += 256) {
        atomicAdd(&d_histp[b*3*NBINS + i], sh[i]);
        atomicAdd(&d_histt[b*3*NBINS + i], sh[3*NBINS + i]);
    }

    // block-reduce L1
    float v = l1;
    for (int o = 16; o; o >>= 1) v += __shfl_down_sync(0xffffffffu, v, o);
    int lane = tid & 31, wid = tid >> 5;
    if (lane == 0) red[wid] = v;
    __syncthreads();
    if (wid == 0) {
        v = (lane < 8) ? red[lane] : 0.f;
        for (int o = 4; o; o >>= 1) v += __shfl_down_sync(0xffffffffu, v, o);
        if (lane == 0) atomicAdd(&d_l1sum, v);
    }
}

// ---------------- SSIM level: fused 5-moment 5x5 conv + reduce -------------
__global__ void k_ssim(size_t off, int Hl, int lvl)
{
    int b = blockIdx.z;
    const float* i1 = d_Lp + off + (size_t)b*Hl*Hl;
    const float* i2 = d_Lt + off + (size_t)b*Hl*Hl;

    __shared__ float t1[12][36];
    __shared__ float t2[12][36];
    __shared__ float wsh[25];
    __shared__ float redS[8], redC[8];

    int tid = threadIdx.y*32 + threadIdx.x;
    if (tid < 25) wsh[tid] = d_win[tid];

    int ox = blockIdx.x*32, oy = blockIdx.y*8;
    for (int i = tid; i < 12*36; i += 256) {
        int r = i/36, c = i%36;
        int gy = oy + r - 2, gx = ox + c - 2;
        float v1 = 0.f, v2 = 0.f;
        if (gy >= 0 && gy < Hl && gx >= 0 && gx < Hl) {
            v1 = i1[(size_t)gy*Hl + gx];
            v2 = i2[(size_t)gy*Hl + gx];
        }
        t1[r][c] = v1;
        t2[r][c] = v2;
    }
    __syncthreads();

    float mu1 = 0.f, mu2 = 0.f, x11 = 0.f, x22 = 0.f, x12 = 0.f;
#pragma unroll
    for (int dy = 0; dy < 5; dy++)
#pragma unroll
        for (int dx = 0; dx < 5; dx++) {
            float w = wsh[dy*5 + dx];
            float a = t1[threadIdx.y + dy][threadIdx.x + dx];
            float c = t2[threadIdx.y + dy][threadIdx.x + dx];
            mu1 += w*a;  mu2 += w*c;
            x11 += w*a*a; x22 += w*c*c; x12 += w*a*c;
        }

    float s1  = x11 - mu1*mu1;
    float s2  = x22 - mu2*mu2;
    float s12 = x12 - mu1*mu2;
    const float C1 = 1e-4f, C2 = 9e-4f;
    float den  = s1 + s2 + C2;
    float num2 = 2.f*s12 + C2;
    float cs   = num2 / den;
    float ssim = ((2.f*mu1*mu2 + C1) * num2) / ((mu1*mu1 + mu2*mu2 + C1) * den);

    float vs = ssim, vc = cs;
    for (int o = 16; o; o >>= 1) {
        vs += __shfl_down_sync(0xffffffffu, vs, o);
        vc += __shfl_down_sync(0xffffffffu, vc, o);
    }
    int lane = tid & 31, wid = tid >> 5;
    if (lane == 0) { redS[wid] = vs; redC[wid] = vc; }
    __syncthreads();
    if (wid == 0) {
        vs = (lane < 8) ? redS[lane] : 0.f;
        vc = (lane < 8) ? redC[lane] : 0.f;
        for (int o = 4; o; o >>= 1) {
            vs += __shfl_down_sync(0xffffffffu, vs, o);
            vc += __shfl_down_sync(0xffffffffu, vc, o);
        }
        if (lane == 0) {
            atomicAdd(&d_ssim_sum[b*5 + lvl], vs);
            atomicAdd(&d_cs_sum[b*5 + lvl], vc);
        }
    }
}

// ---------------- 2x2 average-pool downsample (both streams) ---------------
__global__ void k_down(size_t offi, size_t offo, int Ho)
{
    int b = blockIdx.y;
    float* base = blockIdx.z ? d_Lt : d_Lp;
    int Hi = Ho*2;
    const float* in  = base + offi + (size_t)b*Hi*Hi;
    float*       out = base + offo + (size_t)b*Ho*Ho;
    int idx = blockIdx.x*256 + threadIdx.x;
    if (idx < Ho*Ho) {
        int y = idx / Ho, x = idx % Ho;
        const float* q = in + (size_t)(2*y)*Hi + 2*x;
        out[idx] = 0.25f * (q[0] + q[1] + q[Hi] + q[Hi+1]);
    }
}

// ---------------- final scalar assembly ------------------------------------
__global__ void k_final(float* __restrict__ out)
{
    __shared__ float l1img[8];
    __shared__ float msarr[8];
    int t = threadIdx.x;

    // histogram L1 per image: one warp per image
    int b = t >> 5, lane = t & 31;
    float s = 0.f;
    for (int i = lane; i < 3*NBINS; i += 32) {
        int d = d_histp[b*3*NBINS + i] - d_histt[b*3*NBINS + i];
        s += fabsf((float)d);
    }
    for (int o = 16; o; o >>= 1) s += __shfl_down_sync(0xffffffffu, s, o);
    if (lane == 0) l1img[b] = s * (1.f/768.f);
    __syncthreads();

    if (t < 8) {
        const float wts[5] = {0.0448f, 0.2856f, 0.3001f, 0.2363f, 0.1333f};
        const float cnt[5] = {262144.f, 65536.f, 16384.f, 4096.f, 1024.f};
        float ms = 1.f;
        for (int l = 0; l < 4; l++) {
            float mcs = d_cs_sum[t*5 + l] / cnt[l];
            ms *= powf((mcs + 1.f)*0.5f, wts[l]);
        }
        float mss4 = d_ssim_sum[t*5 + 4] / cnt[4];
        ms *= powf((mss4 + 1.f)*0.5f, wts[4]);
        msarr[t] = 1.f - ms;
    }
    __syncthreads();

    if (t == 0) {
        float hist_loss = 0.f;
        for (int i = 0; i < 8; i++)
            hist_loss += exp2f((float)(i - 8)) * (l1img[i] + 1.f);
        float scaler = (float)(Hdim*Wdim) / 20.f;
        hist_loss = hist_loss / 8.f / scaler;
        float lab_l1 = d_l1sum / (float)(Bn*3*NPIX);
        float sl = 0.f;
        for (int i = 0; i < 8; i++) sl += msarr[i];
        sl *= (1.f/8.f);
        out[0] = lab_l1 + hist_loss;
        out[1] = sl;
    }
}

// ---------------- launch ----------------------------------------------------
extern "C" void kernel_launch(void* const* d_in, const int* in_sizes, int n_in,
                              void* d_out, int out_size)
{
    const float* pred = (const float*)d_in[1];
    const float* tgt  = (const float*)d_in[2];
    float* out = (float*)d_out;

    k_init<<<32, 256>>>();

    dim3 g1(NPIX/256, Bn);
    k_lab<<<g1, 256>>>(pred, tgt);

    const int    Hs[5]  = {512, 256, 128, 64, 32};
    const size_t off[5] = {0, 2097152, 2621440, 2752512, 2785280};

    for (int l = 0; l < 5; l++) {
        int Hl = Hs[l];
        dim3 grid(Hl/32, Hl/8, Bn);
        dim3 blk(32, 8);
        k_ssim<<<grid, blk>>>(off[l], Hl, l);
        if (l < 4) {
            int Ho = Hl/2;
            dim3 gd((Ho*Ho + 255)/256, Bn, 2);
            k_down<<<gd, 256>>>(off[l], off[l+1], Ho);
        }
    }

    k_final<<<1, 256>>>(out);
}

// round 2
// speedup vs baseline: 1.5339x; 1.5339x over previous
#include <cuda_runtime.h>
#include <math.h>

#define Bn    8
#define Hdim  512
#define Wdim  512
#define NPIX  (Hdim*Wdim)
#define NBINS 256

// Separable Gaussian taps: g[i] = exp(-(i-2)^2/4.5)/sum, sigma=1.5
#define G0 0.12007823f
#define G1 0.23388087f
#define G2 0.29208180f
__device__ __constant__ float c_g[5] = {G0, G1, G2, G1, G0};

// Pyramid arenas (elements): L0 @0 (8*262144), L1 @2097152, L2 @2621440,
// L3 @2752512, L4 @2785280
__device__ float d_Lp[2793472];
__device__ float d_Lt[2793472];
__device__ int   d_histp[Bn*3*NBINS];
__device__ int   d_histt[Bn*3*NBINS];
__device__ float d_l1sum;
__device__ float d_ssim_sum[Bn*5];
__device__ float d_cs_sum[Bn*5];

// ---------------- RGB -> normalized LAB helpers ----------------------------
__device__ __forceinline__ float srgb_lin(float x)
{
    if (x <= 0.04045f) return x * (1.f/12.92f);
    float y = (fmaxf(x, 1e-4f) + 0.055f) * (1.f/1.055f);
    return __powf(y, 2.4f);
}

__device__ __forceinline__ float f_lab(float t)
{
    const float e3 = 0.008856451679035631f;   // (6/29)^3
    if (t <= e3) return t * (841.f/108.f) + (4.f/29.f);
    return __powf(fmaxf(t, 1e-4f), 1.f/3.f);
}

__device__ __forceinline__ void rgb2lab_norm(float r, float g, float b,
                                             float& L, float& A, float& Bc)
{
    float lr = srgb_lin(r), lg = srgb_lin(g), lb = srgb_lin(b);
    float X = lr*0.412453f + lg*0.357580f + lb*0.180423f;
    float Y = lr*0.212671f + lg*0.715160f + lb*0.072169f;
    float Z = lr*0.019334f + lg*0.119193f + lb*0.950227f;
    X *= (1.f/0.950456f);
    Z *= (1.f/1.088754f);
    float fx = f_lab(X), fy = f_lab(Y), fz = f_lab(Z);
    float Ll = 116.f*fy - 16.f;
    float Aa = 500.f*(fx - fy);
    float Bb = 200.f*(fy - fz);
    L  = fminf(fmaxf(Ll * 0.01f,                 0.f), 1.f);
    A  = fminf(fmaxf((Aa*(1.f/110.f)+1.f)*0.5f,  0.f), 1.f);
    Bc = fminf(fmaxf((Bb*(1.f/110.f)+1.f)*0.5f,  0.f), 1.f);
}

__device__ __forceinline__ int bin_of(float v)
{
    int b = (int)(v * 256.f);
    return b > 255 ? 255 : b;
}

// ---------------- fused LAB + histogram + L1 + L-channel store -------------
// grid (64, 8) x 256 threads; each thread: 4 iterations of 4 px (float4)
__global__ void k_lab(const float* __restrict__ pred, const float* __restrict__ tgt)
{
    __shared__ int   sh[6*NBINS];
    __shared__ float red[8];
    int b   = blockIdx.y;
    int tid = threadIdx.x;

    for (int i = tid; i < 6*NBINS; i += 256) sh[i] = 0;
    __syncthreads();

    const size_t ibase = (size_t)b*3*NPIX;
    float l1acc = 0.f;

#pragma unroll
    for (int it = 0; it < 4; it++) {
        int p = blockIdx.x*4096 + (it*256 + tid)*4;
        float4 pr = *(const float4*)(pred + ibase + p);
        float4 pg = *(const float4*)(pred + ibase + NPIX + p);
        float4 pb = *(const float4*)(pred + ibase + 2*NPIX + p);
        float4 tr = *(const float4*)(tgt  + ibase + p);
        float4 tg = *(const float4*)(tgt  + ibase + NPIX + p);
        float4 tb = *(const float4*)(tgt  + ibase + 2*NPIX + p);

        float4 plo, tlo;
        float* prf = &pr.x; float* pgf = &pg.x; float* pbf = &pb.x;
        float* trf = &tr.x; float* tgf = &tg.x; float* tbf = &tb.x;
        float* plf = &plo.x; float* tlf = &tlo.x;
#pragma unroll
        for (int j = 0; j < 4; j++) {
            float pl, pa, pbc, tl, ta, tbc;
            rgb2lab_norm(prf[j], pgf[j], pbf[j], pl, pa, pbc);
            rgb2lab_norm(trf[j], tgf[j], tbf[j], tl, ta, tbc);
            plf[j] = pl; tlf[j] = tl;
            atomicAdd(&sh[0*NBINS + bin_of(pl)],  1);
            atomicAdd(&sh[1*NBINS + bin_of(pa)],  1);
            atomicAdd(&sh[2*NBINS + bin_of(pbc)], 1);
            atomicAdd(&sh[3*NBINS + bin_of(tl)],  1);
            atomicAdd(&sh[4*NBINS + bin_of(ta)],  1);
            atomicAdd(&sh[5*NBINS + bin_of(tbc)], 1);
            l1acc += fabsf(pl-tl) + fabsf(pa-ta) + fabsf(pbc-tbc);
        }
        *(float4*)(d_Lp + (size_t)b*NPIX + p) = plo;
        *(float4*)(d_Lt + (size_t)b*NPIX + p) = tlo;
    }

    __syncthreads();   // histogram atomics complete

    for (int i = tid; i < 3*NBINS; i += 256) {
        int hp = sh[i], ht = sh[3*NBINS + i];
        if (hp) atomicAdd(&d_histp[b*3*NBINS + i], hp);
        if (ht) atomicAdd(&d_histt[b*3*NBINS + i], ht);
    }

    // block-reduce L1
    float v = l1acc;
    for (int o = 16; o; o >>= 1) v += __shfl_down_sync(0xffffffffu, v, o);
    int lane = tid & 31, wid = tid >> 5;
    if (lane == 0) red[wid] = v;
    __syncthreads();
    if (wid == 0) {
        v = (lane < 8) ? red[lane] : 0.f;
        for (int o = 4; o; o >>= 1) v += __shfl_down_sync(0xffffffffu, v, o);
        if (lane == 0) atomicAdd(&d_l1sum, v);
    }
}

// ---------------- SSIM level: separable 5-moment conv + reduce + fused pool
template<int POOL>
__global__ void k_ssim(size_t off, size_t offo, int Hl, int lvl)
{
    int b = blockIdx.z;
    const float* i1 = d_Lp + off + (size_t)b*Hl*Hl;
    const float* i2 = d_Lt + off + (size_t)b*Hl*Hl;

    __shared__ float t1[12][36];
    __shared__ float t2[12][36];
    __shared__ float hm1[12][32], hm2[12][32];
    __shared__ float h11[12][32], h22[12][32], h12[12][32];
    __shared__ float redS[8], redC[8];

    int tid = threadIdx.y*32 + threadIdx.x;
    int ox = blockIdx.x*32, oy = blockIdx.y*8;

    // load 12x36 halo tile (zero pad)
    for (int i = tid; i < 12*36; i += 256) {
        int r = i/36, c = i%36;
        int gy = oy + r - 2, gx = ox + c - 2;
        float v1 = 0.f, v2 = 0.f;
        if (gy >= 0 && gy < Hl && gx >= 0 && gx < Hl) {
            v1 = i1[(size_t)gy*Hl + gx];
            v2 = i2[(size_t)gy*Hl + gx];
        }
        t1[r][c] = v1;
        t2[r][c] = v2;
    }
    __syncthreads();

    // horizontal pass: 12x32 outputs
    for (int i = tid; i < 12*32; i += 256) {
        int r = i >> 5, c = i & 31;
        float m1 = 0.f, m2 = 0.f, a11 = 0.f, a22 = 0.f, a12 = 0.f;
#pragma unroll
        for (int k = 0; k < 5; k++) {
            float g = c_g[k];
            float a = t1[r][c+k];
            float q = t2[r][c+k];
            float ga = g*a, gq = g*q;
            m1 += ga;  m2 += gq;
            a11 += ga*a; a22 += gq*q; a12 += ga*q;
        }
        hm1[r][c] = m1; hm2[r][c] = m2;
        h11[r][c] = a11; h22[r][c] = a22; h12[r][c] = a12;
    }
    __syncthreads();

    // vertical pass: one output pixel per thread
    int tx = threadIdx.x, ty = threadIdx.y;
    float mu1 = 0.f, mu2 = 0.f, x11 = 0.f, x22 = 0.f, x12 = 0.f;
#pragma unroll
    for (int k = 0; k < 5; k++) {
        float g = c_g[k];
        mu1 += g*hm1[ty+k][tx];
        mu2 += g*hm2[ty+k][tx];
        x11 += g*h11[ty+k][tx];
        x22 += g*h22[ty+k][tx];
        x12 += g*h12[ty+k][tx];
    }

    float s1  = x11 - mu1*mu1;
    float s2  = x22 - mu2*mu2;
    float s12 = x12 - mu1*mu2;
    const float C1 = 1e-4f, C2 = 9e-4f;
    float den  = s1 + s2 + C2;
    float num2 = 2.f*s12 + C2;
    float cs   = num2 / den;
    float ssim = ((2.f*mu1*mu2 + C1) * num2) / ((mu1*mu1 + mu2*mu2 + C1) * den);

    // fused 2x2 avg-pool into next level (tile interior lives in t1/t2)
    if (POOL && tid < 64) {
        int rp = tid >> 4, cp = tid & 15;
        int Ho = Hl >> 1;
        float p1 = 0.25f*(t1[2*rp+2][2*cp+2] + t1[2*rp+2][2*cp+3] +
                          t1[2*rp+3][2*cp+2] + t1[2*rp+3][2*cp+3]);
        float p2 = 0.25f*(t2[2*rp+2][2*cp+2] + t2[2*rp+2][2*cp+3] +
                          t2[2*rp+3][2*cp+2] + t2[2*rp+3][2*cp+3]);
        size_t o = offo + (size_t)b*Ho*Ho + (size_t)((oy>>1)+rp)*Ho + (ox>>1)+cp;
        d_Lp[o] = p1;
        d_Lt[o] = p2;
    }

    // block reduce ssim & cs
    float vs = ssim, vc = cs;
    for (int o = 16; o; o >>= 1) {
        vs += __shfl_down_sync(0xffffffffu, vs, o);
        vc += __shfl_down_sync(0xffffffffu, vc, o);
    }
    int lane = tid & 31, wid = tid >> 5;
    if (lane == 0) { redS[wid] = vs; redC[wid] = vc; }
    __syncthreads();
    if (wid == 0) {
        vs = (lane < 8) ? redS[lane] : 0.f;
        vc = (lane < 8) ? redC[lane] : 0.f;
        for (int o = 4; o; o >>= 1) {
            vs += __shfl_down_sync(0xffffffffu, vs, o);
            vc += __shfl_down_sync(0xffffffffu, vc, o);
        }
        if (lane == 0) {
            atomicAdd(&d_ssim_sum[b*5 + lvl], vs);
            atomicAdd(&d_cs_sum[b*5 + lvl], vc);
        }
    }
}

// ---------------- final scalar assembly + state re-zero --------------------
__global__ void k_final(float* __restrict__ out)
{
    __shared__ float l1img[8];
    __shared__ float msarr[8];
    int t = threadIdx.x;

    // histogram L1 per image: one warp per image
    int b = t >> 5, lane = t & 31;
    float s = 0.f;
    for (int i = lane; i < 3*NBINS; i += 32) {
        int d = d_histp[b*3*NBINS + i] - d_histt[b*3*NBINS + i];
        s += fabsf((float)d);
    }
    for (int o = 16; o; o >>= 1) s += __shfl_down_sync(0xffffffffu, s, o);
    if (lane == 0) l1img[b] = s * (1.f/768.f);
    __syncthreads();

    if (t < 8) {
        const float wts[5] = {0.0448f, 0.2856f, 0.3001f, 0.2363f, 0.1333f};
        const float cnt[5] = {262144.f, 65536.f, 16384.f, 4096.f, 1024.f};
        float ms = 1.f;
        for (int l = 0; l < 4; l++) {
            float mcs = d_cs_sum[t*5 + l] / cnt[l];
            ms *= powf((mcs + 1.f)*0.5f, wts[l]);
        }
        float mss4 = d_ssim_sum[t*5 + 4] / cnt[4];
        ms *= powf((mss4 + 1.f)*0.5f, wts[4]);
        msarr[t] = 1.f - ms;
    }
    __syncthreads();

    if (t == 0) {
        float hist_loss = 0.f;
        for (int i = 0; i < 8; i++)
            hist_loss += exp2f((float)(i - 8)) * (l1img[i] + 1.f);
        float scaler = (float)(Hdim*Wdim) / 20.f;
        hist_loss = hist_loss / 8.f / scaler;
        float lab_l1 = d_l1sum / (float)(Bn*3*NPIX);
        float sl = 0.f;
        for (int i = 0; i < 8; i++) sl += msarr[i];
        sl *= (1.f/8.f);
        out[0] = lab_l1 + hist_loss;
        out[1] = sl;
    }

    // re-zero accumulators for the next (graph-replayed) invocation;
    // all reads above are complete for this block (single-block kernel).
    for (int i = t; i < Bn*3*NBINS; i += 256) { d_histp[i] = 0; d_histt[i] = 0; }
    if (t < Bn*5) { d_ssim_sum[t] = 0.f; d_cs_sum[t] = 0.f; }
    if (t == 0) d_l1sum = 0.f;
}

// ---------------- launch ----------------------------------------------------
extern "C" void kernel_launch(void* const* d_in, const int* in_sizes, int n_in,
                              void* d_out, int out_size)
{
    const float* pred = (const float*)d_in[1];
    const float* tgt  = (const float*)d_in[2];
    float* out = (float*)d_out;

    dim3 g1(64, Bn);
    k_lab<<<g1, 256>>>(pred, tgt);

    const int    Hs[5]  = {512, 256, 128, 64, 32};
    const size_t off[5] = {0, 2097152, 2621440, 2752512, 2785280};

    for (int l = 0; l < 5; l++) {
        int Hl = Hs[l];
        dim3 grid(Hl/32, Hl/8, Bn);
        dim3 blk(32, 8);
        if (l < 4)
            k_ssim<1><<<grid, blk>>>(off[l], off[l+1], Hl, l);
        else
            k_ssim<0><<<grid, blk>>>(off[l], 0, Hl, l);
    }

    k_final<<<1, 256>>>(out);
}